// round 5
// baseline (speedup 1.0000x reference)
#include <cuda_runtime.h>
#include <cuda_bf16.h>
#include <math.h>

#define T_STEPS 512
#define FUT     64
#define BATCH   1024
#define H       256
#define GRID    128
#define NTH     256
#define NTOT    (GRID * NTH)

// ---------------- device state ----------------
__device__ __align__(16) float d_h1[2][BATCH * H];
__device__ __align__(16) float d_c1[BATCH * H];
__device__ __align__(16) float d_h2[2][BATCH * H];
__device__ __align__(16) float d_c2[BATCH * H];
__device__ float d_h3[BATCH];
__device__ float d_c3[BATCH];

// Packed bf16 hi/lo weight fragments: [jgh(16)][kt(16)][nt(8)][lane(32)] uint4
// uint4 = (b0hi, b1hi, b0lo, b1lo), each uint = 2 bf16 (low half = lower k)
__device__ uint4 d_Bp1 [16 * 16 * 8 * 32];
__device__ uint4 d_Bp2i[16 * 16 * 8 * 32];
__device__ uint4 d_Bp2h[16 * 16 * 8 * 32];

// grid barrier
__device__ unsigned d_barcnt = 0;
__device__ volatile unsigned d_bargen = 0;

__device__ __forceinline__ void grid_sync() {
    __syncthreads();
    if (threadIdx.x == 0) {
        __threadfence();
        unsigned gen = d_bargen;
        if (atomicAdd(&d_barcnt, 1u) == GRID - 1u) {
            atomicExch(&d_barcnt, 0u);
            __threadfence();
            d_bargen = gen + 1u;
        } else {
            while (d_bargen == gen) { __nanosleep(64); }
        }
        __threadfence();
    }
    __syncthreads();
}

__device__ __forceinline__ float sigf(float z) { return 1.0f / (1.0f + expf(-z)); }

__device__ __forceinline__ void mma16816(float* c,
                                         unsigned a0, unsigned a1, unsigned a2, unsigned a3,
                                         unsigned b0, unsigned b1) {
    asm volatile("mma.sync.aligned.m16n8k16.row.col.f32.bf16.bf16.f32 "
                 "{%0,%1,%2,%3}, {%4,%5,%6,%7}, {%8,%9}, {%0,%1,%2,%3};"
                 : "+f"(c[0]), "+f"(c[1]), "+f"(c[2]), "+f"(c[3])
                 : "r"(a0), "r"(a1), "r"(a2), "r"(a3), "r"(b0), "r"(b1));
}

// Stage a 64x256 f32 tile (rows bg*64..) into bf16 hi/lo pair planes, stride 132 words.
__device__ __forceinline__ void stage_tile(unsigned* sAhi, unsigned* sAlo,
                                           const float* src, int bg, int tid) {
    #pragma unroll 4
    for (int i = tid; i < 4096; i += NTH) {
        int row = i >> 6, c4 = i & 63;
        float4 v = reinterpret_cast<const float4*>(src + (bg * 64 + row) * H)[c4];
        __nv_bfloat162 h0 = __floats2bfloat162_rn(v.x, v.y);
        __nv_bfloat162 h1 = __floats2bfloat162_rn(v.z, v.w);
        float lx = v.x - __bfloat162float(h0.x);
        float ly = v.y - __bfloat162float(h0.y);
        float lz = v.z - __bfloat162float(h1.x);
        float lw = v.w - __bfloat162float(h1.y);
        __nv_bfloat162 l0 = __floats2bfloat162_rn(lx, ly);
        __nv_bfloat162 l1 = __floats2bfloat162_rn(lz, lw);
        int o = row * 132 + c4 * 2;
        sAhi[o]     = *reinterpret_cast<unsigned*>(&h0);
        sAhi[o + 1] = *reinterpret_cast<unsigned*>(&h1);
        sAlo[o]     = *reinterpret_cast<unsigned*>(&l0);
        sAlo[o + 1] = *reinterpret_cast<unsigned*>(&l1);
    }
}

// K=256 GEMM: 16 k-steps, 8 n-tiles, 3-pass split precision.
// sAhi/sAlo must already be offset to this warp's 16-row slice (mrow*132).
__device__ __forceinline__ void gemm256(float (*acc)[4],
                                        const unsigned* sAhi, const unsigned* sAlo,
                                        const uint4* bb, int lane) {
    const int r = lane >> 2, c = lane & 3;
    const int i0 = r * 132 + c;
    const int i1 = (r + 8) * 132 + c;
    #pragma unroll 2
    for (int kt = 0; kt < 16; ++kt) {
        const int ko = kt * 8;
        unsigned ah0 = sAhi[i0 + ko],     ah1 = sAhi[i1 + ko];
        unsigned ah2 = sAhi[i0 + ko + 4], ah3 = sAhi[i1 + ko + 4];
        unsigned al0 = sAlo[i0 + ko],     al1 = sAlo[i1 + ko];
        unsigned al2 = sAlo[i0 + ko + 4], al3 = sAlo[i1 + ko + 4];
        const uint4* bk = bb + (kt << 8) + lane;
        uint4 bv[8];
        #pragma unroll
        for (int nt = 0; nt < 8; ++nt) bv[nt] = bk[nt * 32];
        #pragma unroll
        for (int nt = 0; nt < 8; ++nt) {
            mma16816(acc[nt], ah0, ah1, ah2, ah3, bv[nt].x, bv[nt].y);  // hi*hi
            mma16816(acc[nt], al0, al1, al2, al3, bv[nt].x, bv[nt].y);  // lo*hi
            mma16816(acc[nt], ah0, ah1, ah2, ah3, bv[nt].z, bv[nt].w);  // hi*lo
        }
    }
}

__device__ __forceinline__ uint4 packw(const float* W, int u, int k0) {
    const float* wr = W + u * H;
    float w00 = wr[k0], w01 = wr[k0 + 1], w10 = wr[k0 + 8], w11 = wr[k0 + 9];
    __nv_bfloat162 h0 = __floats2bfloat162_rn(w00, w01);
    __nv_bfloat162 h1 = __floats2bfloat162_rn(w10, w11);
    __nv_bfloat162 l0 = __floats2bfloat162_rn(w00 - __bfloat162float(h0.x),
                                              w01 - __bfloat162float(h0.y));
    __nv_bfloat162 l1 = __floats2bfloat162_rn(w10 - __bfloat162float(h1.x),
                                              w11 - __bfloat162float(h1.y));
    uint4 rv;
    rv.x = *reinterpret_cast<unsigned*>(&h0);
    rv.y = *reinterpret_cast<unsigned*>(&h1);
    rv.z = *reinterpret_cast<unsigned*>(&l0);
    rv.w = *reinterpret_cast<unsigned*>(&l1);
    return rv;
}

__global__ void __launch_bounds__(NTH) lstm_kernel(
    const float* __restrict__ x,
    const float* __restrict__ Wih1, const float* __restrict__ Whh1,
    const float* __restrict__ bih1, const float* __restrict__ bhh1,
    const float* __restrict__ Wih2, const float* __restrict__ Whh2,
    const float* __restrict__ bih2, const float* __restrict__ bhh2,
    const float* __restrict__ Wih3, const float* __restrict__ Whh3,
    const float* __restrict__ bih3, const float* __restrict__ bhh3,
    float* __restrict__ out)
{
    extern __shared__ unsigned smem_u[];
    unsigned* sAhi = smem_u;                      // plane 0
    unsigned* sAlo = smem_u + 1 * 64 * 132;       // plane 1
    unsigned* sBhi = smem_u + 2 * 64 * 132;       // plane 2
    unsigned* sBlo = smem_u + 3 * 64 * 132;       // plane 3
    float* s_b1 = reinterpret_cast<float*>(smem_u + 4 * 64 * 132);  // 128
    float* s_w1 = s_b1 + 128;                                       // 128
    float* s_b2 = s_w1 + 128;                                       // 128

    const int tid   = threadIdx.x;
    const int lane  = tid & 31;
    const int warp  = tid >> 5;
    const int cta   = blockIdx.x;
    const int bg    = cta >> 3;          // batch group (64 rows)
    const int jg    = cta & 7;           // 32 j units
    const int nhalf = warp >> 2;         // 0/1 : which 64-col half
    const int mrow  = (warp & 3) * 16;   // warp row base within 64
    const int moff  = mrow * 132;        // warp A-slice offset
    const int jgh   = jg * 2 + nhalf;
    const int gtid  = cta * NTH + tid;

    // -------- init: zero states, pack weights --------
    for (int i = gtid; i < BATCH * H; i += NTOT) {
        d_h1[0][i] = 0.f; d_h1[1][i] = 0.f; d_c1[i] = 0.f;
        d_h2[0][i] = 0.f; d_h2[1][i] = 0.f; d_c2[i] = 0.f;
    }
    if (gtid < BATCH) { d_h3[gtid] = 0.f; d_c3[gtid] = 0.f; }
    for (int idx = gtid; idx < 16 * 16 * 8 * 32; idx += NTOT) {
        int lane_ = idx & 31, nt = (idx >> 5) & 7, kt = (idx >> 8) & 15, jh = idx >> 12;
        int jg_ = jh >> 1, hf = jh & 1;
        int n = lane_ >> 2, cq = lane_ & 3;
        int up = hf * 64 + nt * 8 + n;                 // column within CTA (j*4+gate)
        int u  = (up & 3) * 256 + jg_ * 32 + (up >> 2);
        int k0 = kt * 16 + cq * 2;
        d_Bp1 [idx] = packw(Whh1, u, k0);
        d_Bp2i[idx] = packw(Wih2, u, k0);
        d_Bp2h[idx] = packw(Whh2, u, k0);
    }
    // bias / input-weight tables (per-CTA columns)
    if (tid < 128) {
        int jl = tid >> 2, g = tid & 3;
        int u = g * 256 + jg * 32 + jl;
        s_b1[tid] = bih1[u] + bhh1[u];
        s_w1[tid] = Wih1[u];
        s_b2[tid] = bih2[u] + bhh2[u];
    }
    grid_sync();

    int parity = 0;
    for (int t = 0; t < T_STEPS + FUT; ++t) {
        const float* h1cur = d_h1[parity];
        float*       h1nxt = d_h1[parity ^ 1];
        const float* h2cur = d_h2[parity];
        float*       h2nxt = d_h2[parity ^ 1];

        // ================= phase 1 =================
        stage_tile(sAhi, sAlo, h1cur, bg, tid);
        __syncthreads();
        {
            float acc[8][4];
            #pragma unroll
            for (int nt = 0; nt < 8; ++nt)
                #pragma unroll
                for (int q = 0; q < 4; ++q) acc[nt][q] = 0.f;

            gemm256(acc, sAhi + moff, sAlo + moff, d_Bp1 + (jgh << 12), lane);

            const int q4 = lane & 3;
            #pragma unroll
            for (int nt = 0; nt < 8; ++nt) {
                float s0 = __shfl_xor_sync(0xffffffffu, (q4 & 1) ? acc[nt][0] : acc[nt][2], 1);
                float s1 = __shfl_xor_sync(0xffffffffu, (q4 & 1) ? acc[nt][1] : acc[nt][3], 1);
                float gi, gf, gg, go; int rr;
                if (q4 & 1) { gi = s0; gf = s1; gg = acc[nt][2]; go = acc[nt][3]; rr = (lane >> 2) + 8; }
                else        { gi = acc[nt][0]; gf = acc[nt][1]; gg = s0; go = s1; rr = lane >> 2; }
                int jl = nhalf * 16 + nt * 2 + (q4 >> 1);
                int b  = bg * 64 + mrow + rr;
                int j  = jg * 32 + jl;
                float xin = (t < T_STEPS) ? x[t * BATCH + b] : d_c3[b];
                float zi = gi + xin * s_w1[jl * 4 + 0] + s_b1[jl * 4 + 0];
                float zf = gf + xin * s_w1[jl * 4 + 1] + s_b1[jl * 4 + 1];
                float zg = gg + xin * s_w1[jl * 4 + 2] + s_b1[jl * 4 + 2];
                float zo = go + xin * s_w1[jl * 4 + 3] + s_b1[jl * 4 + 3];
                float co = d_c1[b * H + j];
                float cn = sigf(zf) * co + sigf(zi) * tanhf(zg);
                float hn = sigf(zo) * tanhf(cn);
                d_c1[b * H + j]  = cn;
                h1nxt[b * H + j] = hn;
            }
        }
        grid_sync();

        // ================= phase 2 =================
        stage_tile(sAhi, sAlo, d_c1, bg, tid);
        stage_tile(sBhi, sBlo, h2cur, bg, tid);
        __syncthreads();
        {
            float acc[8][4];
            #pragma unroll
            for (int nt = 0; nt < 8; ++nt)
                #pragma unroll
                for (int q = 0; q < 4; ++q) acc[nt][q] = 0.f;

            gemm256(acc, sAhi + moff, sAlo + moff, d_Bp2i + (jgh << 12), lane);
            gemm256(acc, sBhi + moff, sBlo + moff, d_Bp2h + (jgh << 12), lane);

            const int q4 = lane & 3;
            #pragma unroll
            for (int nt = 0; nt < 8; ++nt) {
                float s0 = __shfl_xor_sync(0xffffffffu, (q4 & 1) ? acc[nt][0] : acc[nt][2], 1);
                float s1 = __shfl_xor_sync(0xffffffffu, (q4 & 1) ? acc[nt][1] : acc[nt][3], 1);
                float gi, gf, gg, go; int rr;
                if (q4 & 1) { gi = s0; gf = s1; gg = acc[nt][2]; go = acc[nt][3]; rr = (lane >> 2) + 8; }
                else        { gi = acc[nt][0]; gf = acc[nt][1]; gg = s0; go = s1; rr = lane >> 2; }
                int jl = nhalf * 16 + nt * 2 + (q4 >> 1);
                int b  = bg * 64 + mrow + rr;
                int j  = jg * 32 + jl;
                float zi = gi + s_b2[jl * 4 + 0];
                float zf = gf + s_b2[jl * 4 + 1];
                float zg = gg + s_b2[jl * 4 + 2];
                float zo = go + s_b2[jl * 4 + 3];
                float co = d_c2[b * H + j];
                float cn = sigf(zf) * co + sigf(zi) * tanhf(zg);
                float hn = sigf(zo) * tanhf(cn);
                d_c2[b * H + j]  = cn;
                h2nxt[b * H + j] = hn;
            }
        }
        grid_sync();

        // ================= phase 3 (H=1), warp-per-batch =================
        {
            int b = cta * 8 + warp;
            const float* c2row = d_c2 + b * H;
            float a0 = 0.f, a1 = 0.f, a2 = 0.f, a3 = 0.f;
            #pragma unroll
            for (int kk = 0; kk < 8; ++kk) {
                int k = kk * 32 + lane;
                float v = c2row[k];
                a0 = fmaf(v, Wih3[0 * H + k], a0);
                a1 = fmaf(v, Wih3[1 * H + k], a1);
                a2 = fmaf(v, Wih3[2 * H + k], a2);
                a3 = fmaf(v, Wih3[3 * H + k], a3);
            }
            #pragma unroll
            for (int o = 16; o > 0; o >>= 1) {
                a0 += __shfl_xor_sync(0xFFFFFFFFu, a0, o);
                a1 += __shfl_xor_sync(0xFFFFFFFFu, a1, o);
                a2 += __shfl_xor_sync(0xFFFFFFFFu, a2, o);
                a3 += __shfl_xor_sync(0xFFFFFFFFu, a3, o);
            }
            if (lane == 0) {
                float h3o = d_h3[b], c3o = d_c3[b];
                float zi = a0 + h3o * Whh3[0] + bih3[0] + bhh3[0];
                float zf = a1 + h3o * Whh3[1] + bih3[1] + bhh3[1];
                float zg = a2 + h3o * Whh3[2] + bih3[2] + bhh3[2];
                float zo = a3 + h3o * Whh3[3] + bih3[3] + bhh3[3];
                float cn = sigf(zf) * c3o + sigf(zi) * tanhf(zg);
                float hn = sigf(zo) * tanhf(cn);
                d_c3[b] = cn;
                d_h3[b] = hn;
                if (t >= T_STEPS) out[b * FUT + (t - T_STEPS)] = cn;
            }
        }
        grid_sync();

        parity ^= 1;
    }
}

extern "C" void kernel_launch(void* const* d_in, const int* in_sizes, int n_in,
                              void* d_out, int out_size) {
    (void)in_sizes; (void)n_in; (void)out_size;
    const float* x    = (const float*)d_in[0];
    const float* Wih1 = (const float*)d_in[1];
    const float* Whh1 = (const float*)d_in[2];
    const float* bih1 = (const float*)d_in[3];
    const float* bhh1 = (const float*)d_in[4];
    const float* Wih2 = (const float*)d_in[5];
    const float* Whh2 = (const float*)d_in[6];
    const float* bih2 = (const float*)d_in[7];
    const float* bhh2 = (const float*)d_in[8];
    const float* Wih3 = (const float*)d_in[9];
    const float* Whh3 = (const float*)d_in[10];
    const float* bih3 = (const float*)d_in[11];
    const float* bhh3 = (const float*)d_in[12];

    const int smem_bytes = (4 * 64 * 132 + 3 * 128) * 4;  // 136704
    cudaFuncSetAttribute(lstm_kernel, cudaFuncAttributeMaxDynamicSharedMemorySize, 137216);
    lstm_kernel<<<GRID, NTH, smem_bytes>>>(x, Wih1, Whh1, bih1, bhh1,
                                           Wih2, Whh2, bih2, bhh2,
                                           Wih3, Whh3, bih3, bhh3,
                                           (float*)d_out);
}